// round 14
// baseline (speedup 1.0000x reference)
#include <cuda_runtime.h>
#include <cstdint>

// ---------------------------------------------------------------------------
// Problem constants
// ---------------------------------------------------------------------------
#define BATCH 2
#define HH 192
#define WW 192
#define EE 10
#define NS 10
#define NITER 300
#define NMID 3
#define FCH 64

#define PIX (BATCH*HH*WW)          // 73728 pixels (per channel)
#define IPIX (4*HH*WW)             // 147456 image-pixels for conv stack
#define SLOT (PIX*2)               // 147456 elements per output slot

// conv_mid tiling
#define TX 64                      // output pixels per tile (one row strip)
#define IPX 66                     // TX + 2 halo
#define CPAD 65                    // padded channel stride for conflict-free LDS
#define CMID_THREADS 512
#define W_SMEM_FLOATS (9*64*64)            // 36864
#define IN_SMEM_FLOATS (3*IPX*CPAD)        // 12870
#define CMID_SMEM_BYTES ((W_SMEM_FLOATS + IN_SMEM_FLOATS)*4)   // 198936
#define TILES_PER_D (2*HH*(WW/TX))         // 2 imgs * 192 rows * 3 xtiles = 1152
#define CMID_GRID_X 144

// ---------------------------------------------------------------------------
// Scratch (device globals: allocation-free)
// ---------------------------------------------------------------------------
__device__ float g_x[PIX*2];
__device__ float g_A[(size_t)IPIX*FCH];
__device__ float g_B[(size_t)IPIX*FCH];

// ---------------------------------------------------------------------------
// Packed f32x2 helpers (conv_mid inner loop)
// ---------------------------------------------------------------------------
__device__ __forceinline__ unsigned long long pack2(float a, float b) {
    unsigned long long r;
    asm("mov.b64 %0, {%1, %2};" : "=l"(r) : "f"(a), "f"(b));
    return r;
}
__device__ __forceinline__ void unpack2(unsigned long long v, float &a, float &b) {
    asm("mov.b64 {%0, %1}, %2;" : "=f"(a), "=f"(b) : "l"(v));
}
__device__ __forceinline__ void ffma2(unsigned long long &d, unsigned long long a,
                                      unsigned long long b) {
    asm("fma.rn.f32x2 %0, %1, %2, %0;" : "+l"(d) : "l"(a), "l"(b));
}

// ---------------------------------------------------------------------------
// XLA:CPU inlined f32 exp (GenerateVF32Exp, Cephes style), emitted with the
// module's FAST flags -> aarch64 backend contracts mul+add into fmla.
// Replicated here with fmaf at every contraction point:
//   fx = floor(fma(x, log2e, 0.5))
//   xr = fma(fx, -c1, x)      ( x - fx*c1 contracted )
//   xr = fma(fx, -c2, xr)     ( xr - fx*c2 contracted; c2 negative )
//   Horner: y = fma(y, xr, c_i) ... y = fma(y, z2, xr) ; y = y + 1
//   result = max(y * 2^n, x0)
// ---------------------------------------------------------------------------
__device__ __forceinline__ float xla_expf(float x0) {
    float x = fminf(fmaxf(x0, -88.3762626647949f), 88.3762626647950f);
    float fx = floorf(fmaf(x, 1.44269504088896341f, 0.5f));
    float xr = fmaf(fx, -0.693359375f, x);            // x - fx*c1
    xr = fmaf(fx, 2.12194440e-4f, xr);                // xr - fx*c2 (c2 = -2.12e-4)
    float z2 = __fmul_rn(xr, xr);
    float y = 1.9875691500E-4f;
    y = fmaf(y, xr, 1.3981999507E-3f);
    y = fmaf(y, xr, 8.3334519073E-3f);
    y = fmaf(y, xr, 4.1665795894E-2f);
    y = fmaf(y, xr, 1.6666665459E-1f);
    y = fmaf(y, xr, 5.0000001201E-1f);
    y = fmaf(y, z2, xr);
    y = __fadd_rn(y, 1.0f);
    int n = (int)fx;                                  // fx integral, in [-15, 0] here
    float s = __int_as_float((n + 127) << 23);        // 2^n
    float r = __fmul_rn(y, s);
    return fmaxf(r, x0);   // tail (no-op for our inputs)
}

// ---------------------------------------------------------------------------
// jr() lowering: XLA:CPU, aarch64, fast-math defaults:
//   exp  : Cephes inline, FMA-contracted (above)
//   body : fmla contraction:
//          r  = fma(m0, e, -b)
//          sm = fma(e, r, sm)
//          sp = fma(((-t)*m0)*e, r, sp)   (leading muls stay separate)
//   mean : honor_division -> TRUE fdiv by 10.0f
//   step : x' = fma(-2, g, x)
// ---------------------------------------------------------------------------

// ---------------------------------------------------------------------------
// 1) Exponential-fit init: 300 GD iterations per pixel
// ---------------------------------------------------------------------------
__global__ __launch_bounds__(256) void fit_kernel2(
    const float* __restrict__ b, const float* __restrict__ tes,
    float* __restrict__ x)
{
    int p = blockIdx.x * 256 + threadIdx.x;
    if (p >= PIX) return;
    int n = p / (HH*WW);

    float bb[EE], nt[EE];
    const float* bp = b + (size_t)p * EE;
#pragma unroll
    for (int e = 0; e < EE; e++) {
        bb[e] = bp[e];
        nt[e] = -tes[n*EE + e];          // exact sign flip, matches neg(t)
    }
    float m0 = 0.f;
#pragma unroll
    for (int e = 0; e < EE; e++) m0 = fmaxf(m0, bb[e]);
    m0 = fminf(fmaxf(m0, 0.0f), 3.0f);
    float p2 = 1.0f;

    for (int it = 0; it < NITER; ++it) {
        float sm = 0.0f, sp = 0.0f;
#pragma unroll
        for (int e = 0; e < EE; e++) {
            float ee = xla_expf(__fmul_rn(nt[e], p2));        // Cephes exp(-t*p2)
            float r  = fmaf(m0, ee, -bb[e]);                  // contracted m0*e-b
            sm = fmaf(ee, r, sm);                             // contracted +e*r
            float A  = __fmul_rn(__fmul_rn(nt[e], m0), ee);   // (-t*m0)*e
            sp = fmaf(A, r, sp);                              // contracted +A*r
        }
        float g0 = __fdiv_rn(sm, 10.0f);                      // mean via true fdiv
        float g1 = __fdiv_rn(sp, 10.0f);
        float m0n = fmaf(-2.0f, g0, m0);                      // x - 2*g (fused)
        float p2n = fmaf(-2.0f, g1, p2);
        m0 = fminf(fmaxf(m0n, 0.0f), 3.0f);
        p2 = fminf(fmaxf(p2n, 0.0f), 10.0f);
    }
    x[2*p]   = m0;
    x[2*p+1] = p2;
}

// ---------------------------------------------------------------------------
// 2) conv_in: 1 -> 64 channels + bias + relu   (x channel d -> h)
// ---------------------------------------------------------------------------
__global__ __launch_bounds__(256) void conv_in_kernel(
    const float* __restrict__ x, float* __restrict__ h,
    const float* __restrict__ Wm, const float* __restrict__ Wp,
    const float* __restrict__ Bm, const float* __restrict__ Bp)
{
    int tid = threadIdx.x;
    int co  = tid & 63;
    int q   = blockIdx.x * 4 + (tid >> 6);     // image-pixel 0..IPIX-1
    if (q >= IPIX) return;
    int d   = q / PIX;                          // denoiser index
    int rem = q - d * PIX;                      // n*36864 + y*192 + xx
    int yx  = rem % (HH*WW);
    int y   = yx / WW, xx = yx % WW;
    int nbase = rem - yx;                       // n*36864

    const float* W = d ? Wp : Wm;
    const float* B = d ? Bp : Bm;
    float acc = B[co];
#pragma unroll
    for (int ky = 0; ky < 3; ky++) {
        int yy = y + ky - 1;
        if ((unsigned)yy >= (unsigned)HH) continue;
#pragma unroll
        for (int kx = 0; kx < 3; kx++) {
            int x2 = xx + kx - 1;
            if ((unsigned)x2 >= (unsigned)WW) continue;
            float v = x[(size_t)(nbase + yy*WW + x2)*2 + d];
            acc = fmaf(v, W[(ky*3 + kx)*64 + co], acc);
        }
    }
    h[((size_t)q << 6) + co] = fmaxf(acc, 0.f);
}

// ---------------------------------------------------------------------------
// 3) conv_mid: 64 -> 64 + bias + relu.  Weights in SMEM, FFMA2 inner loop.
//    grid = (CMID_GRID_X, 2)  blockDim = 512  (64 px  x  8 co-groups of 8)
// ---------------------------------------------------------------------------
extern __shared__ float smem[];

__global__ __launch_bounds__(CMID_THREADS, 1) void conv_mid_kernel(
    const float* __restrict__ in, float* __restrict__ out,
    const float* __restrict__ Wm, const float* __restrict__ Wp,
    const float* __restrict__ Bm, const float* __restrict__ Bp)
{
    float* w_s  = smem;                          // [9][64][64]
    float* in_s = smem + W_SMEM_FLOATS;          // [3][IPX][CPAD]

    int tid = threadIdx.x;
    int d   = blockIdx.y;
    const float* W = d ? Wp : Wm;
    const float* B = d ? Bp : Bm;

    // ---- load weights (9216 float4) ----
    {
        const float4* src = (const float4*)W;
        float4* dst = (float4*)w_s;
        for (int i = tid; i < W_SMEM_FLOATS/4; i += CMID_THREADS) dst[i] = src[i];
    }

    int px = tid & 63;
    int cg = tid >> 6;                           // 0..7 -> co = cg*8 .. cg*8+7

    // packed bias accumulator template
    const float4* b4 = (const float4*)B;
    float4 ba = b4[cg*2], bb4 = b4[cg*2 + 1];
    unsigned long long bias0 = pack2(ba.x, ba.y);
    unsigned long long bias1 = pack2(ba.z, ba.w);
    unsigned long long bias2 = pack2(bb4.x, bb4.y);
    unsigned long long bias3 = pack2(bb4.z, bb4.w);

    const ulonglong2* wu2 = (const ulonglong2*)w_s;   // 16 ull2 per (tap,ci)

    __syncthreads();

    for (int t = blockIdx.x; t < TILES_PER_D; t += CMID_GRID_X) {
        int xt = t % (WW/TX);
        int y  = (t / (WW/TX)) % HH;
        int n  = t / ((WW/TX)*HH);
        int img = d*2 + n;
        int x0 = xt * TX;

        __syncthreads();   // previous tile's reads done before refill
        // ---- fill input halo tile: [3][IPX][CPAD], zero-padded ----
        for (int idx = tid; idx < 3*IPX*16; idx += CMID_THREADS) {
            int ci4 = idx & 15;
            int pp  = (idx >> 4) % IPX;
            int r   = idx / (16*IPX);
            int yy  = y - 1 + r;
            int xg  = x0 - 1 + pp;
            float4 v = make_float4(0.f, 0.f, 0.f, 0.f);
            if ((unsigned)yy < (unsigned)HH && (unsigned)xg < (unsigned)WW)
                v = *(const float4*)(in + (((size_t)(img*HH + yy)*WW + xg) << 6) + (ci4 << 2));
            float* dst = in_s + (r*IPX + pp)*CPAD + (ci4 << 2);
            dst[0] = v.x; dst[1] = v.y; dst[2] = v.z; dst[3] = v.w;
        }
        __syncthreads();

        // ---- compute 8 output channels for pixel (y, x0+px) ----
        unsigned long long acc0 = bias0, acc1 = bias1, acc2 = bias2, acc3 = bias3;
#pragma unroll 1
        for (int tap = 0; tap < 9; ++tap) {
            int ky = tap / 3, kx = tap - ky*3;
            const float* ip = in_s + (ky*IPX + px + kx)*CPAD;
            const ulonglong2* wt = wu2 + tap*1024 + cg*2;
#pragma unroll 8
            for (int ci = 0; ci < 64; ++ci) {
                float iv = ip[ci];
                unsigned long long iv2 = pack2(iv, iv);
                ulonglong2 wa = wt[ci*16];
                ulonglong2 wb = wt[ci*16 + 1];
                ffma2(acc0, iv2, wa.x);
                ffma2(acc1, iv2, wa.y);
                ffma2(acc2, iv2, wb.x);
                ffma2(acc3, iv2, wb.y);
            }
        }
        float r0, r1, r2, r3, r4, r5, r6, r7;
        unpack2(acc0, r0, r1); unpack2(acc1, r2, r3);
        unpack2(acc2, r4, r5); unpack2(acc3, r6, r7);
        float4 o0 = make_float4(fmaxf(r0,0.f), fmaxf(r1,0.f), fmaxf(r2,0.f), fmaxf(r3,0.f));
        float4 o1 = make_float4(fmaxf(r4,0.f), fmaxf(r5,0.f), fmaxf(r6,0.f), fmaxf(r7,0.f));
        float* op = out + (((size_t)(img*HH + y)*WW + x0 + px) << 6) + (cg << 3);
        *(float4*)op       = o0;
        *(float4*)(op + 4) = o1;
    }
}

// ---------------------------------------------------------------------------
// 4) conv_out: 64 -> 1 (+bias), residual x - conv, clamp -> Dx into out[2i]
//    warp per pixel
// ---------------------------------------------------------------------------
__global__ __launch_bounds__(256) void conv_out_kernel(
    const float* __restrict__ h, const float* __restrict__ x,
    const float* __restrict__ Wm, const float* __restrict__ Wp,
    const float* __restrict__ Bm, const float* __restrict__ Bp,
    float* __restrict__ out, int stage)
{
    int lane = threadIdx.x & 31;
    int q = blockIdx.x * 8 + (threadIdx.x >> 5);   // image-pixel
    if (q >= IPIX) return;
    int d   = q / PIX;
    int p   = q - d * PIX;                          // pixel in x/out space
    int yx  = q % (HH*WW);
    int y   = yx / WW, xx = yx % WW;
    int ibase = q - yx;                             // img*36864

    const float* W = d ? Wp : Wm;
    float acc = 0.f;
#pragma unroll
    for (int ky = 0; ky < 3; ky++) {
        int yy = y + ky - 1;
        if ((unsigned)yy >= (unsigned)HH) continue;
#pragma unroll
        for (int kx = 0; kx < 3; kx++) {
            int x2 = xx + kx - 1;
            if ((unsigned)x2 >= (unsigned)WW) continue;
            const float* hp = h + ((size_t)(ibase + yy*WW + x2) << 6);
            const float* wp = W + (ky*3 + kx)*64;
            acc = fmaf(hp[lane],      wp[lane],      acc);
            acc = fmaf(hp[lane + 32], wp[lane + 32], acc);
        }
    }
#pragma unroll
    for (int o = 16; o > 0; o >>= 1)
        acc += __shfl_xor_sync(0xFFFFFFFFu, acc, o);

    if (lane == 0) {
        float xv = x[(size_t)p*2 + d];
        float bo = d ? Bp[0] : Bm[0];
        float v  = xv - (acc + bo);
        v = fminf(fmaxf(v, 0.f), d ? 10.f : 3.f);
        out[(size_t)(2*stage)*SLOT + (size_t)p*2 + d] = v;
    }
}

// ---------------------------------------------------------------------------
// 5) data-consistency update: x = rc(x - mu*(jr(x) + lm*(x - Dx)))
//    writes out[2i+1] (and out[20] on last stage).
//    jr replicated with the same lowering as fit_kernel2.
// ---------------------------------------------------------------------------
__global__ __launch_bounds__(256) void update_kernel(
    float* __restrict__ x, const float* __restrict__ b,
    const float* __restrict__ tes, const float* __restrict__ mu,
    const float* __restrict__ lm, float* __restrict__ out, int stage)
{
    int p = blockIdx.x * 256 + threadIdx.x;
    if (p >= PIX) return;
    int n = p / (HH*WW);

    float m0 = x[2*p], p2 = x[2*p+1];
    const float* bp = b + (size_t)p * EE;

    float sm = 0.0f, sp = 0.0f;
#pragma unroll
    for (int e = 0; e < EE; e++) {
        float ntv = -tes[n*EE + e];
        float ee = xla_expf(__fmul_rn(ntv, p2));
        float r  = fmaf(m0, ee, -bp[e]);
        sm = fmaf(ee, r, sm);
        float A  = __fmul_rn(__fmul_rn(ntv, m0), ee);
        sp = fmaf(A, r, sp);
    }
    float g0 = __fdiv_rn(sm, 10.0f);
    float g1 = __fdiv_rn(sp, 10.0f);

    size_t dxo = (size_t)(2*stage)*SLOT + (size_t)p*2;
    float Dx0 = out[dxo], Dx1 = out[dxo + 1];
    float mui = mu[stage], lmi = lm[stage];

    // x - mu*(g + lm*(x - Dx)) with fast-math contraction:
    //   inner = fma(lm, x-Dx, g) ; x' = fma(-mu, inner, x)
    float m0n = fmaf(-mui, fmaf(lmi, __fsub_rn(m0, Dx0), g0), m0);
    float p2n = fmaf(-mui, fmaf(lmi, __fsub_rn(p2, Dx1), g1), p2);
    m0n = fminf(fmaxf(m0n, 0.f), 3.0f);
    p2n = fminf(fmaxf(p2n, 0.f), 10.0f);

    x[2*p]   = m0n;
    x[2*p+1] = p2n;
    size_t oo = (size_t)(2*stage + 1)*SLOT + (size_t)p*2;
    out[oo]     = m0n;
    out[oo + 1] = p2n;
    if (stage == NS - 1) {
        size_t fo = (size_t)(2*NS)*SLOT + (size_t)p*2;
        out[fo]     = m0n;
        out[fo + 1] = p2n;
    }
}

// ---------------------------------------------------------------------------
// Launch
// ---------------------------------------------------------------------------
extern "C" void kernel_launch(void* const* d_in, const int* in_sizes, int n_in,
                              void* d_out, int out_size)
{
    const float* b      = (const float*)d_in[0];
    const float* tes    = (const float*)d_in[1];
    const float* mu     = (const float*)d_in[2];
    const float* lm     = (const float*)d_in[3];
    const float* Wm_in  = (const float*)d_in[4];
    const float* bm_in  = (const float*)d_in[5];
    const float* Wm_mid = (const float*)d_in[6];
    const float* bm_mid = (const float*)d_in[7];
    const float* Wm_out = (const float*)d_in[8];
    const float* bm_out = (const float*)d_in[9];
    const float* Wp_in  = (const float*)d_in[10];
    const float* bp_in  = (const float*)d_in[11];
    const float* Wp_mid = (const float*)d_in[12];
    const float* bp_mid = (const float*)d_in[13];
    const float* Wp_out = (const float*)d_in[14];
    const float* bp_out = (const float*)d_in[15];
    float* out = (float*)d_out;

    float *xbuf, *A, *B;
    cudaGetSymbolAddress((void**)&xbuf, g_x);
    cudaGetSymbolAddress((void**)&A, g_A);
    cudaGetSymbolAddress((void**)&B, g_B);

    cudaFuncSetAttribute(conv_mid_kernel,
                         cudaFuncAttributeMaxDynamicSharedMemorySize,
                         CMID_SMEM_BYTES);

    fit_kernel2<<<PIX/256, 256>>>(b, tes, xbuf);

    for (int i = 0; i < NS; ++i) {
        conv_in_kernel<<<IPIX/4, 256>>>(
            xbuf, A,
            Wm_in + i*576, Wp_in + i*576,
            bm_in + i*64,  bp_in + i*64);

        const float* wm0 = Wm_mid + (size_t)(i*NMID + 0)*36864;
        const float* wp0 = Wp_mid + (size_t)(i*NMID + 0)*36864;
        const float* bm0 = bm_mid + (i*NMID + 0)*64;
        const float* bp0 = bp_mid + (i*NMID + 0)*64;
        conv_mid_kernel<<<dim3(CMID_GRID_X,2), CMID_THREADS, CMID_SMEM_BYTES>>>(
            A, B, wm0, wp0, bm0, bp0);

        conv_mid_kernel<<<dim3(CMID_GRID_X,2), CMID_THREADS, CMID_SMEM_BYTES>>>(
            B, A, wm0 + 36864, wp0 + 36864, bm0 + 64, bp0 + 64);

        conv_mid_kernel<<<dim3(CMID_GRID_X,2), CMID_THREADS, CMID_SMEM_BYTES>>>(
            A, B, wm0 + 2*36864, wp0 + 2*36864, bm0 + 128, bp0 + 128);

        conv_out_kernel<<<IPIX/8, 256>>>(
            B, xbuf,
            Wm_out + i*576, Wp_out + i*576,
            bm_out + i, bp_out + i,
            out, i);

        update_kernel<<<PIX/256, 256>>>(xbuf, b, tes, mu, lm, out, i);
    }
    (void)in_sizes; (void)n_in; (void)out_size;
}

// round 15
// speedup vs baseline: 1.5669x; 1.5669x over previous
#include <cuda_runtime.h>
#include <cstdint>

// ---------------------------------------------------------------------------
// Problem constants
// ---------------------------------------------------------------------------
#define BATCH 2
#define HH 192
#define WW 192
#define EE 10
#define NS 10
#define NITER 300
#define NMID 3
#define FCH 64

#define PIX (BATCH*HH*WW)          // 73728 pixels (per channel)
#define IPIX (4*HH*WW)             // 147456 image-pixels for conv stack
#define SLOT (PIX*2)               // 147456 elements per output slot

// conv_mid tiling: 2 output rows x 64 px per tile, 512 threads
// thread = (cg 0..15 -> 4 co) x (slot 0..31 -> 2 rows x 16 px-groups of 4 px)
#define TX 64
#define IPX 66                     // TX + 2 halo
#define IR 4                       // 2 rows + 2 halo
#define CPAD 65                    // padded ci stride (bank-conflict ~2-way)
#define CMID_THREADS 512
#define W_SMEM_FLOATS (9*64*64)            // 36864 (144 KB)
#define IN_SMEM_FLOATS (IR*IPX*CPAD)       // 17160 (68.6 KB)
#define CMID_SMEM_BYTES ((W_SMEM_FLOATS + IN_SMEM_FLOATS)*4)   // 216096
#define TILES_PER_D (2*(HH/2)*(WW/TX))     // 2 imgs * 96 row-pairs * 3 = 576
#define CMID_GRID_X 144                    // 4 tiles per block

// ---------------------------------------------------------------------------
// Scratch (device globals: allocation-free)
// ---------------------------------------------------------------------------
__device__ float g_x[PIX*2];
__device__ float g_A[(size_t)IPIX*FCH];
__device__ float g_B[(size_t)IPIX*FCH];

// ---------------------------------------------------------------------------
// Packed f32x2 helpers (conv_mid inner loop)
// ---------------------------------------------------------------------------
__device__ __forceinline__ unsigned long long pack2(float a, float b) {
    unsigned long long r;
    asm("mov.b64 %0, {%1, %2};" : "=l"(r) : "f"(a), "f"(b));
    return r;
}
__device__ __forceinline__ void unpack2(unsigned long long v, float &a, float &b) {
    asm("mov.b64 {%0, %1}, %2;" : "=f"(a), "=f"(b) : "l"(v));
}
__device__ __forceinline__ void ffma2(unsigned long long &d, unsigned long long a,
                                      unsigned long long b) {
    asm("fma.rn.f32x2 %0, %1, %2, %0;" : "+l"(d) : "l"(a), "l"(b));
}

// ---------------------------------------------------------------------------
// XLA:CPU inlined f32 exp (Cephes, FMA-contracted) — BITWISE FROZEN (R13 pass)
// ---------------------------------------------------------------------------
__device__ __forceinline__ float xla_expf(float x0) {
    float x = fminf(fmaxf(x0, -88.3762626647949f), 88.3762626647950f);
    float fx = floorf(fmaf(x, 1.44269504088896341f, 0.5f));
    float xr = fmaf(fx, -0.693359375f, x);
    xr = fmaf(fx, 2.12194440e-4f, xr);
    float z2 = __fmul_rn(xr, xr);
    float y = 1.9875691500E-4f;
    y = fmaf(y, xr, 1.3981999507E-3f);
    y = fmaf(y, xr, 8.3334519073E-3f);
    y = fmaf(y, xr, 4.1665795894E-2f);
    y = fmaf(y, xr, 1.6666665459E-1f);
    y = fmaf(y, xr, 5.0000001201E-1f);
    y = fmaf(y, z2, xr);
    y = __fadd_rn(y, 1.0f);
    int n = (int)fx;
    float s = __int_as_float((n + 127) << 23);
    float r = __fmul_rn(y, s);
    return fmaxf(r, x0);
}

// ---------------------------------------------------------------------------
// 1) Exponential-fit init — BITWISE FROZEN (R13 pass)
// ---------------------------------------------------------------------------
__global__ __launch_bounds__(256) void fit_kernel2(
    const float* __restrict__ b, const float* __restrict__ tes,
    float* __restrict__ x)
{
    int p = blockIdx.x * 256 + threadIdx.x;
    if (p >= PIX) return;
    int n = p / (HH*WW);

    float bb[EE], nt[EE];
    const float* bp = b + (size_t)p * EE;
#pragma unroll
    for (int e = 0; e < EE; e++) {
        bb[e] = bp[e];
        nt[e] = -tes[n*EE + e];
    }
    float m0 = 0.f;
#pragma unroll
    for (int e = 0; e < EE; e++) m0 = fmaxf(m0, bb[e]);
    m0 = fminf(fmaxf(m0, 0.0f), 3.0f);
    float p2 = 1.0f;

    for (int it = 0; it < NITER; ++it) {
        float sm = 0.0f, sp = 0.0f;
#pragma unroll
        for (int e = 0; e < EE; e++) {
            float ee = xla_expf(__fmul_rn(nt[e], p2));
            float r  = fmaf(m0, ee, -bb[e]);
            sm = fmaf(ee, r, sm);
            float A  = __fmul_rn(__fmul_rn(nt[e], m0), ee);
            sp = fmaf(A, r, sp);
        }
        float g0 = __fdiv_rn(sm, 10.0f);
        float g1 = __fdiv_rn(sp, 10.0f);
        float m0n = fmaf(-2.0f, g0, m0);
        float p2n = fmaf(-2.0f, g1, p2);
        m0 = fminf(fmaxf(m0n, 0.0f), 3.0f);
        p2 = fminf(fmaxf(p2n, 0.0f), 10.0f);
    }
    x[2*p]   = m0;
    x[2*p+1] = p2;
}

// ---------------------------------------------------------------------------
// 2) conv_in: 1 -> 64 channels + bias + relu
// ---------------------------------------------------------------------------
__global__ __launch_bounds__(256) void conv_in_kernel(
    const float* __restrict__ x, float* __restrict__ h,
    const float* __restrict__ Wm, const float* __restrict__ Wp,
    const float* __restrict__ Bm, const float* __restrict__ Bp)
{
    int tid = threadIdx.x;
    int co  = tid & 63;
    int q   = blockIdx.x * 4 + (tid >> 6);
    if (q >= IPIX) return;
    int d   = q / PIX;
    int rem = q - d * PIX;
    int yx  = rem % (HH*WW);
    int y   = yx / WW, xx = yx % WW;
    int nbase = rem - yx;

    const float* W = d ? Wp : Wm;
    const float* B = d ? Bp : Bm;
    float acc = B[co];
#pragma unroll
    for (int ky = 0; ky < 3; ky++) {
        int yy = y + ky - 1;
        if ((unsigned)yy >= (unsigned)HH) continue;
#pragma unroll
        for (int kx = 0; kx < 3; kx++) {
            int x2 = xx + kx - 1;
            if ((unsigned)x2 >= (unsigned)WW) continue;
            float v = x[(size_t)(nbase + yy*WW + x2)*2 + d];
            acc = fmaf(v, W[(ky*3 + kx)*64 + co], acc);
        }
    }
    h[((size_t)q << 6) + co] = fmaxf(acc, 0.f);
}

// ---------------------------------------------------------------------------
// 3) conv_mid: 64 -> 64 + bias + relu.
//    512 threads: cg = tid>>5 (4 co), slot = tid&31 (r = slot>>4, pxg = slot&15)
//    Each thread: 4 px x 4 co accumulators; weights amortized over 4 px.
//    Per (ky,ci): 6 input LDS.32 + 3 weight LDS.128 (broadcast) + 24 FFMA2.
// ---------------------------------------------------------------------------
extern __shared__ float smem[];

__global__ __launch_bounds__(CMID_THREADS, 1) void conv_mid_kernel(
    const float* __restrict__ in, float* __restrict__ out,
    const float* __restrict__ Wm, const float* __restrict__ Wp,
    const float* __restrict__ Bm, const float* __restrict__ Bp)
{
    float* w_s  = smem;                          // [9][64][64]  tap-major
    float* in_s = smem + W_SMEM_FLOATS;          // [4][66][CPAD] row,px,ci

    int tid = threadIdx.x;
    int d   = blockIdx.y;
    const float* W = d ? Wp : Wm;
    const float* B = d ? Bp : Bm;

    // ---- load weights (9216 float4) ----
    {
        const float4* src = (const float4*)W;
        float4* dst = (float4*)w_s;
        for (int i = tid; i < W_SMEM_FLOATS/4; i += CMID_THREADS) dst[i] = src[i];
    }

    int slot = tid & 31;
    int cg   = tid >> 5;          // 0..15 -> co = cg*4 .. cg*4+3
    int r    = slot >> 4;         // 0..1  output row within tile
    int pxg  = slot & 15;         // 0..15 -> px = pxg*4 .. pxg*4+3

    const float2* b2 = (const float2*)(B + cg*4);
    float2 bA = b2[0], bB = b2[1];
    unsigned long long bias0 = pack2(bA.x, bA.y);
    unsigned long long bias1 = pack2(bB.x, bB.y);

    for (int t = blockIdx.x; t < TILES_PER_D; t += CMID_GRID_X) {
        int xt = t % (WW/TX);
        int yt = (t / (WW/TX)) % (HH/2);
        int n  = t / ((WW/TX)*(HH/2));
        int img = d*2 + n;
        int x0 = xt * TX;
        int y0 = yt * 2;

        __syncthreads();   // previous tile's reads done before refill
        // ---- fill input halo tile: [4][IPX][CPAD], zero-padded ----
        for (int idx = tid; idx < IR*IPX*16; idx += CMID_THREADS) {
            int ci4 = idx & 15;
            int pp  = (idx >> 4) % IPX;
            int rr  = idx / (16*IPX);
            int yy  = y0 - 1 + rr;
            int xg  = x0 - 1 + pp;
            float4 v = make_float4(0.f, 0.f, 0.f, 0.f);
            if ((unsigned)yy < (unsigned)HH && (unsigned)xg < (unsigned)WW)
                v = *(const float4*)(in + (((size_t)(img*HH + yy)*WW + xg) << 6) + (ci4 << 2));
            float* dst = in_s + (rr*IPX + pp)*CPAD + (ci4 << 2);
            dst[0] = v.x; dst[1] = v.y; dst[2] = v.z; dst[3] = v.w;
        }
        __syncthreads();

        // ---- compute 4 px x 4 co ----
        unsigned long long a00 = bias0, a01 = bias1;
        unsigned long long a10 = bias0, a11 = bias1;
        unsigned long long a20 = bias0, a21 = bias1;
        unsigned long long a30 = bias0, a31 = bias1;

#pragma unroll
        for (int ky = 0; ky < 3; ky++) {
            const float* ib = in_s + ((r + ky)*IPX + pxg*4)*CPAD;
            const float* wb = w_s + (ky*3)*4096 + cg*4;
#pragma unroll 2
            for (int ci = 0; ci < 64; ci++) {
                float v0 = ib[ci];
                float v1 = ib[CPAD   + ci];
                float v2 = ib[2*CPAD + ci];
                float v3 = ib[3*CPAD + ci];
                float v4 = ib[4*CPAD + ci];
                float v5 = ib[5*CPAD + ci];
                unsigned long long p0 = pack2(v0, v0);
                unsigned long long p1 = pack2(v1, v1);
                unsigned long long p2 = pack2(v2, v2);
                unsigned long long p3 = pack2(v3, v3);
                unsigned long long p4 = pack2(v4, v4);
                unsigned long long p5 = pack2(v5, v5);

                ulonglong2 w0 = *(const ulonglong2*)(wb + ci*64);
                ffma2(a00, p0, w0.x); ffma2(a01, p0, w0.y);
                ffma2(a10, p1, w0.x); ffma2(a11, p1, w0.y);
                ffma2(a20, p2, w0.x); ffma2(a21, p2, w0.y);
                ffma2(a30, p3, w0.x); ffma2(a31, p3, w0.y);

                ulonglong2 w1 = *(const ulonglong2*)(wb + 4096 + ci*64);
                ffma2(a00, p1, w1.x); ffma2(a01, p1, w1.y);
                ffma2(a10, p2, w1.x); ffma2(a11, p2, w1.y);
                ffma2(a20, p3, w1.x); ffma2(a21, p3, w1.y);
                ffma2(a30, p4, w1.x); ffma2(a31, p4, w1.y);

                ulonglong2 w2 = *(const ulonglong2*)(wb + 8192 + ci*64);
                ffma2(a00, p2, w2.x); ffma2(a01, p2, w2.y);
                ffma2(a10, p3, w2.x); ffma2(a11, p3, w2.y);
                ffma2(a20, p4, w2.x); ffma2(a21, p4, w2.y);
                ffma2(a30, p5, w2.x); ffma2(a31, p5, w2.y);
            }
        }

        // ---- relu + store: 4 px x float4 ----
        int y = y0 + r;
        float* op = out + (((size_t)(img*HH + y)*WW + x0 + pxg*4) << 6) + cg*4;
        float c0, c1, c2, c3;
        unpack2(a00, c0, c1); unpack2(a01, c2, c3);
        *(float4*)(op)        = make_float4(fmaxf(c0,0.f), fmaxf(c1,0.f), fmaxf(c2,0.f), fmaxf(c3,0.f));
        unpack2(a10, c0, c1); unpack2(a11, c2, c3);
        *(float4*)(op + 64)   = make_float4(fmaxf(c0,0.f), fmaxf(c1,0.f), fmaxf(c2,0.f), fmaxf(c3,0.f));
        unpack2(a20, c0, c1); unpack2(a21, c2, c3);
        *(float4*)(op + 128)  = make_float4(fmaxf(c0,0.f), fmaxf(c1,0.f), fmaxf(c2,0.f), fmaxf(c3,0.f));
        unpack2(a30, c0, c1); unpack2(a31, c2, c3);
        *(float4*)(op + 192)  = make_float4(fmaxf(c0,0.f), fmaxf(c1,0.f), fmaxf(c2,0.f), fmaxf(c3,0.f));
    }
}

// ---------------------------------------------------------------------------
// 4) conv_out: 64 -> 1 (+bias), residual x - conv, clamp -> Dx into out[2i]
// ---------------------------------------------------------------------------
__global__ __launch_bounds__(256) void conv_out_kernel(
    const float* __restrict__ h, const float* __restrict__ x,
    const float* __restrict__ Wm, const float* __restrict__ Wp,
    const float* __restrict__ Bm, const float* __restrict__ Bp,
    float* __restrict__ out, int stage)
{
    int lane = threadIdx.x & 31;
    int q = blockIdx.x * 8 + (threadIdx.x >> 5);
    if (q >= IPIX) return;
    int d   = q / PIX;
    int p   = q - d * PIX;
    int yx  = q % (HH*WW);
    int y   = yx / WW, xx = yx % WW;
    int ibase = q - yx;

    const float* W = d ? Wp : Wm;
    float acc = 0.f;
#pragma unroll
    for (int ky = 0; ky < 3; ky++) {
        int yy = y + ky - 1;
        if ((unsigned)yy >= (unsigned)HH) continue;
#pragma unroll
        for (int kx = 0; kx < 3; kx++) {
            int x2 = xx + kx - 1;
            if ((unsigned)x2 >= (unsigned)WW) continue;
            const float* hp = h + ((size_t)(ibase + yy*WW + x2) << 6);
            const float* wp = W + (ky*3 + kx)*64;
            acc = fmaf(hp[lane],      wp[lane],      acc);
            acc = fmaf(hp[lane + 32], wp[lane + 32], acc);
        }
    }
#pragma unroll
    for (int o = 16; o > 0; o >>= 1)
        acc += __shfl_xor_sync(0xFFFFFFFFu, acc, o);

    if (lane == 0) {
        float xv = x[(size_t)p*2 + d];
        float bo = d ? Bp[0] : Bm[0];
        float v  = xv - (acc + bo);
        v = fminf(fmaxf(v, 0.f), d ? 10.f : 3.f);
        out[(size_t)(2*stage)*SLOT + (size_t)p*2 + d] = v;
    }
}

// ---------------------------------------------------------------------------
// 5) data-consistency update — jr arithmetic BITWISE FROZEN (R13 pass)
// ---------------------------------------------------------------------------
__global__ __launch_bounds__(256) void update_kernel(
    float* __restrict__ x, const float* __restrict__ b,
    const float* __restrict__ tes, const float* __restrict__ mu,
    const float* __restrict__ lm, float* __restrict__ out, int stage)
{
    int p = blockIdx.x * 256 + threadIdx.x;
    if (p >= PIX) return;
    int n = p / (HH*WW);

    float m0 = x[2*p], p2 = x[2*p+1];
    const float* bp = b + (size_t)p * EE;

    float sm = 0.0f, sp = 0.0f;
#pragma unroll
    for (int e = 0; e < EE; e++) {
        float ntv = -tes[n*EE + e];
        float ee = xla_expf(__fmul_rn(ntv, p2));
        float r  = fmaf(m0, ee, -bp[e]);
        sm = fmaf(ee, r, sm);
        float A  = __fmul_rn(__fmul_rn(ntv, m0), ee);
        sp = fmaf(A, r, sp);
    }
    float g0 = __fdiv_rn(sm, 10.0f);
    float g1 = __fdiv_rn(sp, 10.0f);

    size_t dxo = (size_t)(2*stage)*SLOT + (size_t)p*2;
    float Dx0 = out[dxo], Dx1 = out[dxo + 1];
    float mui = mu[stage], lmi = lm[stage];

    float m0n = fmaf(-mui, fmaf(lmi, __fsub_rn(m0, Dx0), g0), m0);
    float p2n = fmaf(-mui, fmaf(lmi, __fsub_rn(p2, Dx1), g1), p2);
    m0n = fminf(fmaxf(m0n, 0.f), 3.0f);
    p2n = fminf(fmaxf(p2n, 0.f), 10.0f);

    x[2*p]   = m0n;
    x[2*p+1] = p2n;
    size_t oo = (size_t)(2*stage + 1)*SLOT + (size_t)p*2;
    out[oo]     = m0n;
    out[oo + 1] = p2n;
    if (stage == NS - 1) {
        size_t fo = (size_t)(2*NS)*SLOT + (size_t)p*2;
        out[fo]     = m0n;
        out[fo + 1] = p2n;
    }
}

// ---------------------------------------------------------------------------
// Launch
// ---------------------------------------------------------------------------
extern "C" void kernel_launch(void* const* d_in, const int* in_sizes, int n_in,
                              void* d_out, int out_size)
{
    const float* b      = (const float*)d_in[0];
    const float* tes    = (const float*)d_in[1];
    const float* mu     = (const float*)d_in[2];
    const float* lm     = (const float*)d_in[3];
    const float* Wm_in  = (const float*)d_in[4];
    const float* bm_in  = (const float*)d_in[5];
    const float* Wm_mid = (const float*)d_in[6];
    const float* bm_mid = (const float*)d_in[7];
    const float* Wm_out = (const float*)d_in[8];
    const float* bm_out = (const float*)d_in[9];
    const float* Wp_in  = (const float*)d_in[10];
    const float* bp_in  = (const float*)d_in[11];
    const float* Wp_mid = (const float*)d_in[12];
    const float* bp_mid = (const float*)d_in[13];
    const float* Wp_out = (const float*)d_in[14];
    const float* bp_out = (const float*)d_in[15];
    float* out = (float*)d_out;

    float *xbuf, *A, *B;
    cudaGetSymbolAddress((void**)&xbuf, g_x);
    cudaGetSymbolAddress((void**)&A, g_A);
    cudaGetSymbolAddress((void**)&B, g_B);

    cudaFuncSetAttribute(conv_mid_kernel,
                         cudaFuncAttributeMaxDynamicSharedMemorySize,
                         CMID_SMEM_BYTES);

    fit_kernel2<<<PIX/256, 256>>>(b, tes, xbuf);

    for (int i = 0; i < NS; ++i) {
        conv_in_kernel<<<IPIX/4, 256>>>(
            xbuf, A,
            Wm_in + i*576, Wp_in + i*576,
            bm_in + i*64,  bp_in + i*64);

        const float* wm0 = Wm_mid + (size_t)(i*NMID + 0)*36864;
        const float* wp0 = Wp_mid + (size_t)(i*NMID + 0)*36864;
        const float* bm0 = bm_mid + (i*NMID + 0)*64;
        const float* bp0 = bp_mid + (i*NMID + 0)*64;
        conv_mid_kernel<<<dim3(CMID_GRID_X,2), CMID_THREADS, CMID_SMEM_BYTES>>>(
            A, B, wm0, wp0, bm0, bp0);

        conv_mid_kernel<<<dim3(CMID_GRID_X,2), CMID_THREADS, CMID_SMEM_BYTES>>>(
            B, A, wm0 + 36864, wp0 + 36864, bm0 + 64, bp0 + 64);

        conv_mid_kernel<<<dim3(CMID_GRID_X,2), CMID_THREADS, CMID_SMEM_BYTES>>>(
            A, B, wm0 + 2*36864, wp0 + 2*36864, bm0 + 128, bp0 + 128);

        conv_out_kernel<<<IPIX/8, 256>>>(
            B, xbuf,
            Wm_out + i*576, Wp_out + i*576,
            bm_out + i, bp_out + i,
            out, i);

        update_kernel<<<PIX/256, 256>>>(xbuf, b, tes, mu, lm, out, i);
    }
    (void)in_sizes; (void)n_in; (void)out_size;
}

// round 16
// speedup vs baseline: 1.8145x; 1.1581x over previous
#include <cuda_runtime.h>
#include <cstdint>

// ---------------------------------------------------------------------------
// Problem constants
// ---------------------------------------------------------------------------
#define BATCH 2
#define HH 192
#define WW 192
#define EE 10
#define NS 10
#define NITER 300
#define NMID 3
#define FCH 64

#define PIX (BATCH*HH*WW)          // 73728
#define IPIX (4*HH*WW)             // 147456
#define SLOT (PIX*2)

// conv_mid tiling v3: 2 rows x 64 px, 256 threads
// thread = cg (tid>>4, 16 groups of 4 co) x r ((tid>>3)&1) x pxg (tid&7, 8 px each)
#define TX 64
#define IPX 66                     // TX + 2 halo
#define IR 4                       // 2 rows + 2 halo
#define PXP 68                     // padded px stride (66 + 2)
#define CMID_THREADS 256
#define W_SMEM_FLOATS (9*64*64)            // 36864 (144 KB), layout [tap][ci][co]
#define IN_SMEM_FLOATS (64*IR*PXP)         // 17408 (69.6 KB), layout [ci][row][px]
#define CMID_SMEM_BYTES ((W_SMEM_FLOATS + IN_SMEM_FLOATS)*4)   // 217088
#define TILES_PER_D (2*(HH/2)*(WW/TX))     // 576
#define CMID_GRID_X 144

// ---------------------------------------------------------------------------
// Scratch (device globals: allocation-free)
// ---------------------------------------------------------------------------
__device__ float g_x[PIX*2];
__device__ float g_A[(size_t)IPIX*FCH];
__device__ float g_B[(size_t)IPIX*FCH];

// ---------------------------------------------------------------------------
// Packed f32x2 helpers
// ---------------------------------------------------------------------------
__device__ __forceinline__ unsigned long long pack2(float a, float b) {
    unsigned long long r;
    asm("mov.b64 %0, {%1, %2};" : "=l"(r) : "f"(a), "f"(b));
    return r;
}
__device__ __forceinline__ void unpack2(unsigned long long v, float &a, float &b) {
    asm("mov.b64 {%0, %1}, %2;" : "=f"(a), "=f"(b) : "l"(v));
}
__device__ __forceinline__ void ffma2(unsigned long long &d, unsigned long long a,
                                      unsigned long long b) {
    asm("fma.rn.f32x2 %0, %1, %2, %0;" : "+l"(d) : "l"(a), "l"(b));
}

// ---------------------------------------------------------------------------
// XLA:CPU inlined f32 exp (Cephes, FMA-contracted) — BITWISE FROZEN (R13 pass)
// ---------------------------------------------------------------------------
__device__ __forceinline__ float xla_expf(float x0) {
    float x = fminf(fmaxf(x0, -88.3762626647949f), 88.3762626647950f);
    float fx = floorf(fmaf(x, 1.44269504088896341f, 0.5f));
    float xr = fmaf(fx, -0.693359375f, x);
    xr = fmaf(fx, 2.12194440e-4f, xr);
    float z2 = __fmul_rn(xr, xr);
    float y = 1.9875691500E-4f;
    y = fmaf(y, xr, 1.3981999507E-3f);
    y = fmaf(y, xr, 8.3334519073E-3f);
    y = fmaf(y, xr, 4.1665795894E-2f);
    y = fmaf(y, xr, 1.6666665459E-1f);
    y = fmaf(y, xr, 5.0000001201E-1f);
    y = fmaf(y, z2, xr);
    y = __fadd_rn(y, 1.0f);
    int n = (int)fx;
    float s = __int_as_float((n + 127) << 23);
    float r = __fmul_rn(y, s);
    return fmaxf(r, x0);
}

// ---------------------------------------------------------------------------
// 1) Exponential-fit init — BITWISE FROZEN (R13 pass)
// ---------------------------------------------------------------------------
__global__ __launch_bounds__(256) void fit_kernel2(
    const float* __restrict__ b, const float* __restrict__ tes,
    float* __restrict__ x)
{
    int p = blockIdx.x * 256 + threadIdx.x;
    if (p >= PIX) return;
    int n = p / (HH*WW);

    float bb[EE], nt[EE];
    const float* bp = b + (size_t)p * EE;
#pragma unroll
    for (int e = 0; e < EE; e++) {
        bb[e] = bp[e];
        nt[e] = -tes[n*EE + e];
    }
    float m0 = 0.f;
#pragma unroll
    for (int e = 0; e < EE; e++) m0 = fmaxf(m0, bb[e]);
    m0 = fminf(fmaxf(m0, 0.0f), 3.0f);
    float p2 = 1.0f;

    for (int it = 0; it < NITER; ++it) {
        float sm = 0.0f, sp = 0.0f;
#pragma unroll
        for (int e = 0; e < EE; e++) {
            float ee = xla_expf(__fmul_rn(nt[e], p2));
            float r  = fmaf(m0, ee, -bb[e]);
            sm = fmaf(ee, r, sm);
            float A  = __fmul_rn(__fmul_rn(nt[e], m0), ee);
            sp = fmaf(A, r, sp);
        }
        float g0 = __fdiv_rn(sm, 10.0f);
        float g1 = __fdiv_rn(sp, 10.0f);
        float m0n = fmaf(-2.0f, g0, m0);
        float p2n = fmaf(-2.0f, g1, p2);
        m0 = fminf(fmaxf(m0n, 0.0f), 3.0f);
        p2 = fminf(fmaxf(p2n, 0.0f), 10.0f);
    }
    x[2*p]   = m0;
    x[2*p+1] = p2;
}

// ---------------------------------------------------------------------------
// 2) conv_in: 1 -> 64 channels + bias + relu
// ---------------------------------------------------------------------------
__global__ __launch_bounds__(256) void conv_in_kernel(
    const float* __restrict__ x, float* __restrict__ h,
    const float* __restrict__ Wm, const float* __restrict__ Wp,
    const float* __restrict__ Bm, const float* __restrict__ Bp)
{
    int tid = threadIdx.x;
    int co  = tid & 63;
    int q   = blockIdx.x * 4 + (tid >> 6);
    if (q >= IPIX) return;
    int d   = q / PIX;
    int rem = q - d * PIX;
    int yx  = rem % (HH*WW);
    int y   = yx / WW, xx = yx % WW;
    int nbase = rem - yx;

    const float* W = d ? Wp : Wm;
    const float* B = d ? Bp : Bm;
    float acc = B[co];
#pragma unroll
    for (int ky = 0; ky < 3; ky++) {
        int yy = y + ky - 1;
        if ((unsigned)yy >= (unsigned)HH) continue;
#pragma unroll
        for (int kx = 0; kx < 3; kx++) {
            int x2 = xx + kx - 1;
            if ((unsigned)x2 >= (unsigned)WW) continue;
            float v = x[(size_t)(nbase + yy*WW + x2)*2 + d];
            acc = fmaf(v, W[(ky*3 + kx)*64 + co], acc);
        }
    }
    h[((size_t)q << 6) + co] = fmaxf(acc, 0.f);
}

// ---------------------------------------------------------------------------
// 3) conv_mid v3: 64 -> 64 + bias + relu.
//    256 threads: cg = tid>>4 (4 co), r = (tid>>3)&1, pxg = tid&7 (8 px).
//    Input smem TRANSPOSED: in_s[ci][row][px] (PXP=68) so a thread's 10-px
//    window is contiguous -> 2x LDS.128 + 2x LDS.32 per (ky,ci).
//    Weights via LDS.32 broadcast (1 wavefront each).
// ---------------------------------------------------------------------------
extern __shared__ float smem[];

__global__ __launch_bounds__(CMID_THREADS, 1) void conv_mid_kernel(
    const float* __restrict__ in, float* __restrict__ out,
    const float* __restrict__ Wm, const float* __restrict__ Wp,
    const float* __restrict__ Bm, const float* __restrict__ Bp)
{
    float* w_s  = smem;                          // [9][64][64]  [tap][ci][co]
    float* in_s = smem + W_SMEM_FLOATS;          // [64][4][68]  [ci][row][px]

    int tid = threadIdx.x;
    int d   = blockIdx.y;
    const float* W = d ? Wp : Wm;
    const float* B = d ? Bp : Bm;

    // ---- load weights (9216 float4) ----
    {
        const float4* src = (const float4*)W;
        float4* dst = (float4*)w_s;
        for (int i = tid; i < W_SMEM_FLOATS/4; i += CMID_THREADS) dst[i] = src[i];
    }

    int cg  = tid >> 4;           // 0..15 -> co = cg*4 .. cg*4+3
    int r   = (tid >> 3) & 1;     // output row within tile
    int pxg = tid & 7;            // 0..7 -> px = pxg*8 .. pxg*8+7

    const float2* b2 = (const float2*)(B + cg*4);
    float2 bA = b2[0], bB = b2[1];
    unsigned long long bias0 = pack2(bA.x, bA.y);
    unsigned long long bias1 = pack2(bB.x, bB.y);

    for (int t = blockIdx.x; t < TILES_PER_D; t += CMID_GRID_X) {
        int xt = t % (WW/TX);
        int yt = (t / (WW/TX)) % (HH/2);
        int n  = t / ((WW/TX)*(HH/2));
        int img = d*2 + n;
        int x0 = xt * TX;
        int y0 = yt * 2;

        __syncthreads();   // previous tile's reads done before refill
        // ---- fill transposed input tile: in_s[ci][row][s], s = px-(x0-1) ----
        // idx -> (pp, rr, ci4): pp in low bits => lanes write contiguous px.
        for (int idx = tid; idx < IPX*IR*16; idx += CMID_THREADS) {
            int pp   = idx % IPX;
            int rest = idx / IPX;
            int rr   = rest & 3;
            int ci4  = rest >> 2;           // 0..15
            int yy  = y0 - 1 + rr;
            int xg  = x0 - 1 + pp;
            float4 v = make_float4(0.f, 0.f, 0.f, 0.f);
            if ((unsigned)yy < (unsigned)HH && (unsigned)xg < (unsigned)WW)
                v = *(const float4*)(in + (((size_t)(img*HH + yy)*WW + xg) << 6) + (ci4 << 2));
            int base = ((ci4*4)*IR + rr)*PXP + pp;
            in_s[base]             = v.x;
            in_s[base + IR*PXP]    = v.y;
            in_s[base + 2*IR*PXP]  = v.z;
            in_s[base + 3*IR*PXP]  = v.w;
        }
        __syncthreads();

        // ---- compute 8 px x 4 co ----
        unsigned long long a0[8], a1[8];
#pragma unroll
        for (int j = 0; j < 8; j++) { a0[j] = bias0; a1[j] = bias1; }

#pragma unroll
        for (int ky = 0; ky < 3; ky++) {
            const float* ip = in_s + (r + ky)*PXP + pxg*8;   // + ci*IR*PXP
            const float* wb = w_s + (ky*3)*4096 + cg*4;      // + kx*4096 + ci*64
            for (int ci = 0; ci < 64; ci++) {
                const float* ipc = ip + ci*(IR*PXP);
                float4 A4 = *(const float4*)(ipc);
                float4 B4 = *(const float4*)(ipc + 4);
                float  c8 = ipc[8];
                float  c9 = ipc[9];
                unsigned long long v[10];
                v[0] = pack2(A4.x, A4.x); v[1] = pack2(A4.y, A4.y);
                v[2] = pack2(A4.z, A4.z); v[3] = pack2(A4.w, A4.w);
                v[4] = pack2(B4.x, B4.x); v[5] = pack2(B4.y, B4.y);
                v[6] = pack2(B4.z, B4.z); v[7] = pack2(B4.w, B4.w);
                v[8] = pack2(c8, c8);     v[9] = pack2(c9, c9);

                const float* wc = wb + ci*64;
#pragma unroll
                for (int kx = 0; kx < 3; kx++) {
                    float w0 = wc[kx*4096];
                    float w1 = wc[kx*4096 + 1];
                    float w2 = wc[kx*4096 + 2];
                    float w3 = wc[kx*4096 + 3];
                    unsigned long long wp01 = pack2(w0, w1);
                    unsigned long long wp23 = pack2(w2, w3);
#pragma unroll
                    for (int j = 0; j < 8; j++) {
                        ffma2(a0[j], v[j + kx], wp01);
                        ffma2(a1[j], v[j + kx], wp23);
                    }
                }
            }
        }

        // ---- relu + store: 8 px x float4 ----
        int y = y0 + r;
        float* op = out + (((size_t)(img*HH + y)*WW + x0 + pxg*8) << 6) + cg*4;
        float c0, c1, c2, c3;
#pragma unroll
        for (int j = 0; j < 8; j++) {
            unpack2(a0[j], c0, c1); unpack2(a1[j], c2, c3);
            *(float4*)(op + (size_t)j*64) =
                make_float4(fmaxf(c0,0.f), fmaxf(c1,0.f), fmaxf(c2,0.f), fmaxf(c3,0.f));
        }
    }
}

// ---------------------------------------------------------------------------
// 4) conv_out: 64 -> 1 (+bias), residual x - conv, clamp -> Dx into out[2i]
// ---------------------------------------------------------------------------
__global__ __launch_bounds__(256) void conv_out_kernel(
    const float* __restrict__ h, const float* __restrict__ x,
    const float* __restrict__ Wm, const float* __restrict__ Wp,
    const float* __restrict__ Bm, const float* __restrict__ Bp,
    float* __restrict__ out, int stage)
{
    int lane = threadIdx.x & 31;
    int q = blockIdx.x * 8 + (threadIdx.x >> 5);
    if (q >= IPIX) return;
    int d   = q / PIX;
    int p   = q - d * PIX;
    int yx  = q % (HH*WW);
    int y   = yx / WW, xx = yx % WW;
    int ibase = q - yx;

    const float* W = d ? Wp : Wm;
    float acc = 0.f;
#pragma unroll
    for (int ky = 0; ky < 3; ky++) {
        int yy = y + ky - 1;
        if ((unsigned)yy >= (unsigned)HH) continue;
#pragma unroll
        for (int kx = 0; kx < 3; kx++) {
            int x2 = xx + kx - 1;
            if ((unsigned)x2 >= (unsigned)WW) continue;
            const float* hp = h + ((size_t)(ibase + yy*WW + x2) << 6);
            const float* wp = W + (ky*3 + kx)*64;
            acc = fmaf(hp[lane],      wp[lane],      acc);
            acc = fmaf(hp[lane + 32], wp[lane + 32], acc);
        }
    }
#pragma unroll
    for (int o = 16; o > 0; o >>= 1)
        acc += __shfl_xor_sync(0xFFFFFFFFu, acc, o);

    if (lane == 0) {
        float xv = x[(size_t)p*2 + d];
        float bo = d ? Bp[0] : Bm[0];
        float v  = xv - (acc + bo);
        v = fminf(fmaxf(v, 0.f), d ? 10.f : 3.f);
        out[(size_t)(2*stage)*SLOT + (size_t)p*2 + d] = v;
    }
}

// ---------------------------------------------------------------------------
// 5) data-consistency update — jr arithmetic BITWISE FROZEN (R13 pass)
// ---------------------------------------------------------------------------
__global__ __launch_bounds__(256) void update_kernel(
    float* __restrict__ x, const float* __restrict__ b,
    const float* __restrict__ tes, const float* __restrict__ mu,
    const float* __restrict__ lm, float* __restrict__ out, int stage)
{
    int p = blockIdx.x * 256 + threadIdx.x;
    if (p >= PIX) return;
    int n = p / (HH*WW);

    float m0 = x[2*p], p2 = x[2*p+1];
    const float* bp = b + (size_t)p * EE;

    float sm = 0.0f, sp = 0.0f;
#pragma unroll
    for (int e = 0; e < EE; e++) {
        float ntv = -tes[n*EE + e];
        float ee = xla_expf(__fmul_rn(ntv, p2));
        float r  = fmaf(m0, ee, -bp[e]);
        sm = fmaf(ee, r, sm);
        float A  = __fmul_rn(__fmul_rn(ntv, m0), ee);
        sp = fmaf(A, r, sp);
    }
    float g0 = __fdiv_rn(sm, 10.0f);
    float g1 = __fdiv_rn(sp, 10.0f);

    size_t dxo = (size_t)(2*stage)*SLOT + (size_t)p*2;
    float Dx0 = out[dxo], Dx1 = out[dxo + 1];
    float mui = mu[stage], lmi = lm[stage];

    float m0n = fmaf(-mui, fmaf(lmi, __fsub_rn(m0, Dx0), g0), m0);
    float p2n = fmaf(-mui, fmaf(lmi, __fsub_rn(p2, Dx1), g1), p2);
    m0n = fminf(fmaxf(m0n, 0.f), 3.0f);
    p2n = fminf(fmaxf(p2n, 0.f), 10.0f);

    x[2*p]   = m0n;
    x[2*p+1] = p2n;
    size_t oo = (size_t)(2*stage + 1)*SLOT + (size_t)p*2;
    out[oo]     = m0n;
    out[oo + 1] = p2n;
    if (stage == NS - 1) {
        size_t fo = (size_t)(2*NS)*SLOT + (size_t)p*2;
        out[fo]     = m0n;
        out[fo + 1] = p2n;
    }
}

// ---------------------------------------------------------------------------
// Launch
// ---------------------------------------------------------------------------
extern "C" void kernel_launch(void* const* d_in, const int* in_sizes, int n_in,
                              void* d_out, int out_size)
{
    const float* b      = (const float*)d_in[0];
    const float* tes    = (const float*)d_in[1];
    const float* mu     = (const float*)d_in[2];
    const float* lm     = (const float*)d_in[3];
    const float* Wm_in  = (const float*)d_in[4];
    const float* bm_in  = (const float*)d_in[5];
    const float* Wm_mid = (const float*)d_in[6];
    const float* bm_mid = (const float*)d_in[7];
    const float* Wm_out = (const float*)d_in[8];
    const float* bm_out = (const float*)d_in[9];
    const float* Wp_in  = (const float*)d_in[10];
    const float* bp_in  = (const float*)d_in[11];
    const float* Wp_mid = (const float*)d_in[12];
    const float* bp_mid = (const float*)d_in[13];
    const float* Wp_out = (const float*)d_in[14];
    const float* bp_out = (const float*)d_in[15];
    float* out = (float*)d_out;

    float *xbuf, *A, *B;
    cudaGetSymbolAddress((void**)&xbuf, g_x);
    cudaGetSymbolAddress((void**)&A, g_A);
    cudaGetSymbolAddress((void**)&B, g_B);

    cudaFuncSetAttribute(conv_mid_kernel,
                         cudaFuncAttributeMaxDynamicSharedMemorySize,
                         CMID_SMEM_BYTES);

    fit_kernel2<<<PIX/256, 256>>>(b, tes, xbuf);

    for (int i = 0; i < NS; ++i) {
        conv_in_kernel<<<IPIX/4, 256>>>(
            xbuf, A,
            Wm_in + i*576, Wp_in + i*576,
            bm_in + i*64,  bp_in + i*64);

        const float* wm0 = Wm_mid + (size_t)(i*NMID + 0)*36864;
        const float* wp0 = Wp_mid + (size_t)(i*NMID + 0)*36864;
        const float* bm0 = bm_mid + (i*NMID + 0)*64;
        const float* bp0 = bp_mid + (i*NMID + 0)*64;
        conv_mid_kernel<<<dim3(CMID_GRID_X,2), CMID_THREADS, CMID_SMEM_BYTES>>>(
            A, B, wm0, wp0, bm0, bp0);

        conv_mid_kernel<<<dim3(CMID_GRID_X,2), CMID_THREADS, CMID_SMEM_BYTES>>>(
            B, A, wm0 + 36864, wp0 + 36864, bm0 + 64, bp0 + 64);

        conv_mid_kernel<<<dim3(CMID_GRID_X,2), CMID_THREADS, CMID_SMEM_BYTES>>>(
            A, B, wm0 + 2*36864, wp0 + 2*36864, bm0 + 128, bp0 + 128);

        conv_out_kernel<<<IPIX/8, 256>>>(
            B, xbuf,
            Wm_out + i*576, Wp_out + i*576,
            bm_out + i, bp_out + i,
            out, i);

        update_kernel<<<PIX/256, 256>>>(xbuf, b, tes, mu, lm, out, i);
    }
    (void)in_sizes; (void)n_in; (void)out_size;
}

// round 17
// speedup vs baseline: 1.8385x; 1.0132x over previous
#include <cuda_runtime.h>
#include <cstdint>

// ---------------------------------------------------------------------------
// Problem constants
// ---------------------------------------------------------------------------
#define BATCH 2
#define HH 192
#define WW 192
#define EE 10
#define NS 10
#define NITER 300
#define NMID 3
#define FCH 64

#define PIX (BATCH*HH*WW)          // 73728
#define IPIX (4*HH*WW)             // 147456
#define SLOT (PIX*2)

// conv_mid tiling v4: 2 rows x 64 px, 256 threads
// thread = cg (tid>>4, 16 groups of 4 co) x r ((tid>>3)&1) x pxg (tid&7, 8 px)
#define TX 64
#define IPX 66                     // TX + 2 halo
#define IR 4                       // 2 rows + 2 halo
#define PXP 68                     // padded px stride
#define CMID_THREADS 256
#define W_SMEM_FLOATS (9*64*64)            // 36864 (144 KB), [tap][ci][co]
#define IN_SMEM_FLOATS (65*IR*PXP)         // 17680 (70.7 KB), [ci][row][px] + 1 dummy ci (prefetch overrun)
#define CMID_SMEM_BYTES ((W_SMEM_FLOATS + IN_SMEM_FLOATS)*4)   // 218176
#define TILES_PER_D (2*(HH/2)*(WW/TX))     // 576
#define CMID_GRID_X 144

// ---------------------------------------------------------------------------
// Scratch (device globals: allocation-free)
// ---------------------------------------------------------------------------
__device__ float g_x[PIX*2];
__device__ float g_A[(size_t)IPIX*FCH];
__device__ float g_B[(size_t)IPIX*FCH];

// ---------------------------------------------------------------------------
// Packed f32x2 helpers
// ---------------------------------------------------------------------------
__device__ __forceinline__ unsigned long long pack2(float a, float b) {
    unsigned long long r;
    asm("mov.b64 %0, {%1, %2};" : "=l"(r) : "f"(a), "f"(b));
    return r;
}
__device__ __forceinline__ void unpack2(unsigned long long v, float &a, float &b) {
    asm("mov.b64 {%0, %1}, %2;" : "=f"(a), "=f"(b) : "l"(v));
}
__device__ __forceinline__ void ffma2(unsigned long long &d, unsigned long long a,
                                      unsigned long long b) {
    asm("fma.rn.f32x2 %0, %1, %2, %0;" : "+l"(d) : "l"(a), "l"(b));
}

// ---------------------------------------------------------------------------
// XLA:CPU inlined f32 exp (Cephes, FMA-contracted) — BITWISE FROZEN (R13 pass)
// ---------------------------------------------------------------------------
__device__ __forceinline__ float xla_expf(float x0) {
    float x = fminf(fmaxf(x0, -88.3762626647949f), 88.3762626647950f);
    float fx = floorf(fmaf(x, 1.44269504088896341f, 0.5f));
    float xr = fmaf(fx, -0.693359375f, x);
    xr = fmaf(fx, 2.12194440e-4f, xr);
    float z2 = __fmul_rn(xr, xr);
    float y = 1.9875691500E-4f;
    y = fmaf(y, xr, 1.3981999507E-3f);
    y = fmaf(y, xr, 8.3334519073E-3f);
    y = fmaf(y, xr, 4.1665795894E-2f);
    y = fmaf(y, xr, 1.6666665459E-1f);
    y = fmaf(y, xr, 5.0000001201E-1f);
    y = fmaf(y, z2, xr);
    y = __fadd_rn(y, 1.0f);
    int n = (int)fx;
    float s = __int_as_float((n + 127) << 23);
    float r = __fmul_rn(y, s);
    return fmaxf(r, x0);
}

// ---------------------------------------------------------------------------
// 1) Exponential-fit init — BITWISE FROZEN (R13 pass)
// ---------------------------------------------------------------------------
__global__ __launch_bounds__(256) void fit_kernel2(
    const float* __restrict__ b, const float* __restrict__ tes,
    float* __restrict__ x)
{
    int p = blockIdx.x * 256 + threadIdx.x;
    if (p >= PIX) return;
    int n = p / (HH*WW);

    float bb[EE], nt[EE];
    const float* bp = b + (size_t)p * EE;
#pragma unroll
    for (int e = 0; e < EE; e++) {
        bb[e] = bp[e];
        nt[e] = -tes[n*EE + e];
    }
    float m0 = 0.f;
#pragma unroll
    for (int e = 0; e < EE; e++) m0 = fmaxf(m0, bb[e]);
    m0 = fminf(fmaxf(m0, 0.0f), 3.0f);
    float p2 = 1.0f;

    for (int it = 0; it < NITER; ++it) {
        float sm = 0.0f, sp = 0.0f;
#pragma unroll
        for (int e = 0; e < EE; e++) {
            float ee = xla_expf(__fmul_rn(nt[e], p2));
            float r  = fmaf(m0, ee, -bb[e]);
            sm = fmaf(ee, r, sm);
            float A  = __fmul_rn(__fmul_rn(nt[e], m0), ee);
            sp = fmaf(A, r, sp);
        }
        float g0 = __fdiv_rn(sm, 10.0f);
        float g1 = __fdiv_rn(sp, 10.0f);
        float m0n = fmaf(-2.0f, g0, m0);
        float p2n = fmaf(-2.0f, g1, p2);
        m0 = fminf(fmaxf(m0n, 0.0f), 3.0f);
        p2 = fminf(fmaxf(p2n, 0.0f), 10.0f);
    }
    x[2*p]   = m0;
    x[2*p+1] = p2;
}

// ---------------------------------------------------------------------------
// 2) conv_in: 1 -> 64 channels + bias + relu
// ---------------------------------------------------------------------------
__global__ __launch_bounds__(256) void conv_in_kernel(
    const float* __restrict__ x, float* __restrict__ h,
    const float* __restrict__ Wm, const float* __restrict__ Wp,
    const float* __restrict__ Bm, const float* __restrict__ Bp)
{
    int tid = threadIdx.x;
    int co  = tid & 63;
    int q   = blockIdx.x * 4 + (tid >> 6);
    if (q >= IPIX) return;
    int d   = q / PIX;
    int rem = q - d * PIX;
    int yx  = rem % (HH*WW);
    int y   = yx / WW, xx = yx % WW;
    int nbase = rem - yx;

    const float* W = d ? Wp : Wm;
    const float* B = d ? Bp : Bm;
    float acc = B[co];
#pragma unroll
    for (int ky = 0; ky < 3; ky++) {
        int yy = y + ky - 1;
        if ((unsigned)yy >= (unsigned)HH) continue;
#pragma unroll
        for (int kx = 0; kx < 3; kx++) {
            int x2 = xx + kx - 1;
            if ((unsigned)x2 >= (unsigned)WW) continue;
            float v = x[(size_t)(nbase + yy*WW + x2)*2 + d];
            acc = fmaf(v, W[(ky*3 + kx)*64 + co], acc);
        }
    }
    h[((size_t)q << 6) + co] = fmaxf(acc, 0.f);
}

// ---------------------------------------------------------------------------
// 3) conv_mid v4: weights via LDS.128, input window software-pipelined.
// ---------------------------------------------------------------------------
extern __shared__ float smem[];

__global__ __launch_bounds__(CMID_THREADS, 1) void conv_mid_kernel(
    const float* __restrict__ in, float* __restrict__ out,
    const float* __restrict__ Wm, const float* __restrict__ Wp,
    const float* __restrict__ Bm, const float* __restrict__ Bp)
{
    float* w_s  = smem;                          // [9][64][64]  [tap][ci][co]
    float* in_s = smem + W_SMEM_FLOATS;          // [65][4][68]  [ci][row][px]

    int tid = threadIdx.x;
    int d   = blockIdx.y;
    const float* W = d ? Wp : Wm;
    const float* B = d ? Bp : Bm;

    // ---- load weights (9216 float4) ----
    {
        const float4* src = (const float4*)W;
        float4* dst = (float4*)w_s;
        for (int i = tid; i < W_SMEM_FLOATS/4; i += CMID_THREADS) dst[i] = src[i];
    }

    int cg  = tid >> 4;           // 0..15 -> co = cg*4 .. cg*4+3
    int r   = (tid >> 3) & 1;     // output row within tile
    int pxg = tid & 7;            // 0..7 -> px = pxg*8 .. pxg*8+7

    const float2* b2 = (const float2*)(B + cg*4);
    float2 bA = b2[0], bB = b2[1];
    unsigned long long bias0 = pack2(bA.x, bA.y);
    unsigned long long bias1 = pack2(bB.x, bB.y);

    for (int t = blockIdx.x; t < TILES_PER_D; t += CMID_GRID_X) {
        int xt = t % (WW/TX);
        int yt = (t / (WW/TX)) % (HH/2);
        int n  = t / ((WW/TX)*(HH/2));
        int img = d*2 + n;
        int x0 = xt * TX;
        int y0 = yt * 2;

        __syncthreads();   // previous tile's reads done before refill
        // ---- fill transposed input tile (ci slots 0..63; slot 64 = junk ok) ----
        for (int idx = tid; idx < IPX*IR*16; idx += CMID_THREADS) {
            int pp   = idx % IPX;
            int rest = idx / IPX;
            int rr   = rest & 3;
            int ci4  = rest >> 2;           // 0..15
            int yy  = y0 - 1 + rr;
            int xg  = x0 - 1 + pp;
            float4 v = make_float4(0.f, 0.f, 0.f, 0.f);
            if ((unsigned)yy < (unsigned)HH && (unsigned)xg < (unsigned)WW)
                v = *(const float4*)(in + (((size_t)(img*HH + yy)*WW + xg) << 6) + (ci4 << 2));
            int base = ((ci4*4)*IR + rr)*PXP + pp;
            in_s[base]             = v.x;
            in_s[base + IR*PXP]    = v.y;
            in_s[base + 2*IR*PXP]  = v.z;
            in_s[base + 3*IR*PXP]  = v.w;
        }
        __syncthreads();

        // ---- compute 8 px x 4 co ----
        unsigned long long a0[8], a1[8];
#pragma unroll
        for (int j = 0; j < 8; j++) { a0[j] = bias0; a1[j] = bias1; }

#pragma unroll
        for (int ky = 0; ky < 3; ky++) {
            const float* ip = in_s + (r + ky)*PXP + pxg*8;       // + ci*IR*PXP
            const float4* wb = (const float4*)(w_s + (ky*3)*4096 + cg*4);
            // wb index: (kx*4096 + ci*64)/4 = kx*1024 + ci*16

            // prologue: prefetch ci=0 window
            float4 A4 = *(const float4*)(ip);
            float4 B4 = *(const float4*)(ip + 4);
            float  c8 = ip[8];
            float  c9 = ip[9];

#pragma unroll 4
            for (int ci = 0; ci < 64; ci++) {
                // prefetch next window (slot 64 is a dummy; values unused)
                const float* ipn = ip + (ci + 1)*(IR*PXP);
                float4 nA = *(const float4*)(ipn);
                float4 nB = *(const float4*)(ipn + 4);
                float  n8 = ipn[8];
                float  n9 = ipn[9];

                // weights: 3x LDS.128 (4 co each)
                float4 w0 = wb[ci*16];
                float4 w1 = wb[1024 + ci*16];
                float4 w2 = wb[2048 + ci*16];

                unsigned long long v[10];
                v[0] = pack2(A4.x, A4.x); v[1] = pack2(A4.y, A4.y);
                v[2] = pack2(A4.z, A4.z); v[3] = pack2(A4.w, A4.w);
                v[4] = pack2(B4.x, B4.x); v[5] = pack2(B4.y, B4.y);
                v[6] = pack2(B4.z, B4.z); v[7] = pack2(B4.w, B4.w);
                v[8] = pack2(c8, c8);     v[9] = pack2(c9, c9);

                unsigned long long wp;
                wp = pack2(w0.x, w0.y);
#pragma unroll
                for (int j = 0; j < 8; j++) ffma2(a0[j], v[j], wp);
                wp = pack2(w0.z, w0.w);
#pragma unroll
                for (int j = 0; j < 8; j++) ffma2(a1[j], v[j], wp);
                wp = pack2(w1.x, w1.y);
#pragma unroll
                for (int j = 0; j < 8; j++) ffma2(a0[j], v[j + 1], wp);
                wp = pack2(w1.z, w1.w);
#pragma unroll
                for (int j = 0; j < 8; j++) ffma2(a1[j], v[j + 1], wp);
                wp = pack2(w2.x, w2.y);
#pragma unroll
                for (int j = 0; j < 8; j++) ffma2(a0[j], v[j + 2], wp);
                wp = pack2(w2.z, w2.w);
#pragma unroll
                for (int j = 0; j < 8; j++) ffma2(a1[j], v[j + 2], wp);

                A4 = nA; B4 = nB; c8 = n8; c9 = n9;
            }
        }

        // ---- relu + store: 8 px x float4 ----
        int y = y0 + r;
        float* op = out + (((size_t)(img*HH + y)*WW + x0 + pxg*8) << 6) + cg*4;
        float c0, c1, c2, c3;
#pragma unroll
        for (int j = 0; j < 8; j++) {
            unpack2(a0[j], c0, c1); unpack2(a1[j], c2, c3);
            *(float4*)(op + (size_t)j*64) =
                make_float4(fmaxf(c0,0.f), fmaxf(c1,0.f), fmaxf(c2,0.f), fmaxf(c3,0.f));
        }
    }
}

// ---------------------------------------------------------------------------
// 4) conv_out: 64 -> 1 (+bias), residual x - conv, clamp -> Dx into out[2i]
// ---------------------------------------------------------------------------
__global__ __launch_bounds__(256) void conv_out_kernel(
    const float* __restrict__ h, const float* __restrict__ x,
    const float* __restrict__ Wm, const float* __restrict__ Wp,
    const float* __restrict__ Bm, const float* __restrict__ Bp,
    float* __restrict__ out, int stage)
{
    int lane = threadIdx.x & 31;
    int q = blockIdx.x * 8 + (threadIdx.x >> 5);
    if (q >= IPIX) return;
    int d   = q / PIX;
    int p   = q - d * PIX;
    int yx  = q % (HH*WW);
    int y   = yx / WW, xx = yx % WW;
    int ibase = q - yx;

    const float* W = d ? Wp : Wm;
    float acc = 0.f;
#pragma unroll
    for (int ky = 0; ky < 3; ky++) {
        int yy = y + ky - 1;
        if ((unsigned)yy >= (unsigned)HH) continue;
#pragma unroll
        for (int kx = 0; kx < 3; kx++) {
            int x2 = xx + kx - 1;
            if ((unsigned)x2 >= (unsigned)WW) continue;
            const float* hp = h + ((size_t)(ibase + yy*WW + x2) << 6);
            const float* wp = W + (ky*3 + kx)*64;
            acc = fmaf(hp[lane],      wp[lane],      acc);
            acc = fmaf(hp[lane + 32], wp[lane + 32], acc);
        }
    }
#pragma unroll
    for (int o = 16; o > 0; o >>= 1)
        acc += __shfl_xor_sync(0xFFFFFFFFu, acc, o);

    if (lane == 0) {
        float xv = x[(size_t)p*2 + d];
        float bo = d ? Bp[0] : Bm[0];
        float v  = xv - (acc + bo);
        v = fminf(fmaxf(v, 0.f), d ? 10.f : 3.f);
        out[(size_t)(2*stage)*SLOT + (size_t)p*2 + d] = v;
    }
}

// ---------------------------------------------------------------------------
// 5) data-consistency update — jr arithmetic BITWISE FROZEN (R13 pass)
// ---------------------------------------------------------------------------
__global__ __launch_bounds__(256) void update_kernel(
    float* __restrict__ x, const float* __restrict__ b,
    const float* __restrict__ tes, const float* __restrict__ mu,
    const float* __restrict__ lm, float* __restrict__ out, int stage)
{
    int p = blockIdx.x * 256 + threadIdx.x;
    if (p >= PIX) return;
    int n = p / (HH*WW);

    float m0 = x[2*p], p2 = x[2*p+1];
    const float* bp = b + (size_t)p * EE;

    float sm = 0.0f, sp = 0.0f;
#pragma unroll
    for (int e = 0; e < EE; e++) {
        float ntv = -tes[n*EE + e];
        float ee = xla_expf(__fmul_rn(ntv, p2));
        float r  = fmaf(m0, ee, -bp[e]);
        sm = fmaf(ee, r, sm);
        float A  = __fmul_rn(__fmul_rn(ntv, m0), ee);
        sp = fmaf(A, r, sp);
    }
    float g0 = __fdiv_rn(sm, 10.0f);
    float g1 = __fdiv_rn(sp, 10.0f);

    size_t dxo = (size_t)(2*stage)*SLOT + (size_t)p*2;
    float Dx0 = out[dxo], Dx1 = out[dxo + 1];
    float mui = mu[stage], lmi = lm[stage];

    float m0n = fmaf(-mui, fmaf(lmi, __fsub_rn(m0, Dx0), g0), m0);
    float p2n = fmaf(-mui, fmaf(lmi, __fsub_rn(p2, Dx1), g1), p2);
    m0n = fminf(fmaxf(m0n, 0.f), 3.0f);
    p2n = fminf(fmaxf(p2n, 0.f), 10.0f);

    x[2*p]   = m0n;
    x[2*p+1] = p2n;
    size_t oo = (size_t)(2*stage + 1)*SLOT + (size_t)p*2;
    out[oo]     = m0n;
    out[oo + 1] = p2n;
    if (stage == NS - 1) {
        size_t fo = (size_t)(2*NS)*SLOT + (size_t)p*2;
        out[fo]     = m0n;
        out[fo + 1] = p2n;
    }
}

// ---------------------------------------------------------------------------
// Launch
// ---------------------------------------------------------------------------
extern "C" void kernel_launch(void* const* d_in, const int* in_sizes, int n_in,
                              void* d_out, int out_size)
{
    const float* b      = (const float*)d_in[0];
    const float* tes    = (const float*)d_in[1];
    const float* mu     = (const float*)d_in[2];
    const float* lm     = (const float*)d_in[3];
    const float* Wm_in  = (const float*)d_in[4];
    const float* bm_in  = (const float*)d_in[5];
    const float* Wm_mid = (const float*)d_in[6];
    const float* bm_mid = (const float*)d_in[7];
    const float* Wm_out = (const float*)d_in[8];
    const float* bm_out = (const float*)d_in[9];
    const float* Wp_in  = (const float*)d_in[10];
    const float* bp_in  = (const float*)d_in[11];
    const float* Wp_mid = (const float*)d_in[12];
    const float* bp_mid = (const float*)d_in[13];
    const float* Wp_out = (const float*)d_in[14];
    const float* bp_out = (const float*)d_in[15];
    float* out = (float*)d_out;

    float *xbuf, *A, *B;
    cudaGetSymbolAddress((void**)&xbuf, g_x);
    cudaGetSymbolAddress((void**)&A, g_A);
    cudaGetSymbolAddress((void**)&B, g_B);

    cudaFuncSetAttribute(conv_mid_kernel,
                         cudaFuncAttributeMaxDynamicSharedMemorySize,
                         CMID_SMEM_BYTES);

    fit_kernel2<<<PIX/256, 256>>>(b, tes, xbuf);

    for (int i = 0; i < NS; ++i) {
        conv_in_kernel<<<IPIX/4, 256>>>(
            xbuf, A,
            Wm_in + i*576, Wp_in + i*576,
            bm_in + i*64,  bp_in + i*64);

        const float* wm0 = Wm_mid + (size_t)(i*NMID + 0)*36864;
        const float* wp0 = Wp_mid + (size_t)(i*NMID + 0)*36864;
        const float* bm0 = bm_mid + (i*NMID + 0)*64;
        const float* bp0 = bp_mid + (i*NMID + 0)*64;
        conv_mid_kernel<<<dim3(CMID_GRID_X,2), CMID_THREADS, CMID_SMEM_BYTES>>>(
            A, B, wm0, wp0, bm0, bp0);

        conv_mid_kernel<<<dim3(CMID_GRID_X,2), CMID_THREADS, CMID_SMEM_BYTES>>>(
            B, A, wm0 + 36864, wp0 + 36864, bm0 + 64, bp0 + 64);

        conv_mid_kernel<<<dim3(CMID_GRID_X,2), CMID_THREADS, CMID_SMEM_BYTES>>>(
            A, B, wm0 + 2*36864, wp0 + 2*36864, bm0 + 128, bp0 + 128);

        conv_out_kernel<<<IPIX/8, 256>>>(
            B, xbuf,
            Wm_out + i*576, Wp_out + i*576,
            bm_out + i, bp_out + i,
            out, i);

        update_kernel<<<PIX/256, 256>>>(xbuf, b, tes, mu, lm, out, i);
    }
    (void)in_sizes; (void)n_in; (void)out_size;
}